// round 13
// baseline (speedup 1.0000x reference)
#include <cuda_runtime.h>
#include <cuda_fp16.h>
#include <cstdint>

#define DEVINL __device__ __forceinline__

// ---------------- problem constants ----------------
constexpr int BATCH = 8, CIN = 256, COUT = 256, HH = 64, WW = 64;
constexpr int HW   = HH * WW;      // 4096
constexpr int KTOT = 9 * CIN;      // 2304
constexpr int SDIM = 512;

// ---------------- scratch ----------------
__device__ __align__(256) __half g_A [BATCH * COUT * KTOT];   // modulated weights, [b][o][tap*256+c]
__device__ __align__(256) __half g_xt[BATCH * HW * CIN];      // x transposed: [b][pixel][channel]
__device__ float g_s[BATCH * CIN];

// ---------------- helpers ----------------
DEVINL uint32_t s2u(const void* p) {
    uint32_t a;
    asm("{ .reg .u64 t; cvta.to.shared.u64 t, %1; cvt.u32.u64 %0, t; }" : "=r"(a) : "l"(p));
    return a;
}
DEVINL uint32_t swz(uint32_t o) { return o ^ ((o >> 3) & 0x70); }  // 128B XOR swizzle

DEVINL void cp16(uint32_t dst, const void* src, uint32_t sz) {
    asm volatile("cp.async.cg.shared.global [%0], [%1], 16, %2;"
                 :: "r"(dst), "l"(src), "r"(sz));
}
DEVINL void cp_commit() { asm volatile("cp.async.commit_group;"); }

DEVINL void ldsm4(uint32_t* r, uint32_t addr) {
    asm volatile("ldmatrix.sync.aligned.m8n8.x4.shared.b16 {%0,%1,%2,%3}, [%4];"
                 : "=r"(r[0]), "=r"(r[1]), "=r"(r[2]), "=r"(r[3]) : "r"(addr));
}
DEVINL void mma16816(float* c, const uint32_t* a, uint32_t b0, uint32_t b1) {
    asm volatile("mma.sync.aligned.m16n8k16.row.col.f32.f16.f16.f32 "
                 "{%0,%1,%2,%3}, {%4,%5,%6,%7}, {%8,%9}, {%0,%1,%2,%3};"
                 : "+f"(c[0]), "+f"(c[1]), "+f"(c[2]), "+f"(c[3])
                 : "r"(a[0]), "r"(a[1]), "r"(a[2]), "r"(a[3]), "r"(b0), "r"(b1));
}

// ---------------- prep kernel A: x transpose (+ style GEMV in guard blocks) ----
// Block: 32 px x 64 ch, 256 threads. Stores are 16B coalesced.
// Blocks (bx==0 && by==0) additionally compute g_s[b][*] (style modulation).
__global__ void k_xt(const float* __restrict__ x,
                     const float* __restrict__ style,
                     const float* __restrict__ mod_w,
                     const float* __restrict__ mod_b) {
    __shared__ float tile[64][33];
    const int b  = blockIdx.z;
    const int c0 = blockIdx.y * 64;
    const int p0 = blockIdx.x * 32;
    const int t  = threadIdx.x;

    // style GEMV: 8 guard blocks (one per batch), thread t -> channel t
    if (blockIdx.x == 0 && blockIdx.y == 0) {
        const float* st = style + b * SDIM;
        const float* wr = mod_w + (size_t)t * SDIM;
        float a0 = 0.f, a1 = 0.f, a2 = 0.f, a3 = 0.f;
        #pragma unroll 4
        for (int d = 0; d < SDIM; d += 4) {
            a0 += st[d]     * wr[d];
            a1 += st[d + 1] * wr[d + 1];
            a2 += st[d + 2] * wr[d + 2];
            a3 += st[d + 3] * wr[d + 3];
        }
        g_s[b * CIN + t] = (a0 + a1 + a2 + a3) * 0.04419417382415922f + mod_b[t];
    }

    // load: warp ty=t>>5 handles 8 channels, lanes = px
    const int tx = t & 31, ty = t >> 5;
    #pragma unroll
    for (int j = 0; j < 8; j++)
        tile[ty * 8 + j][tx] = x[((size_t)b * CIN + c0 + ty * 8 + j) * HW + p0 + tx];
    __syncthreads();

    // store: thread = (px = t>>3, q = t&7) -> 8 halves = 16B coalesced
    const int px = t >> 3, q = t & 7;
    __half h[8];
    #pragma unroll
    for (int j = 0; j < 8; j++)
        h[j] = __float2half(tile[q * 8 + j][px]);
    *reinterpret_cast<uint4*>(
        &g_xt[((size_t)b * HW + p0 + px) * CIN + c0 + q * 8]) = *reinterpret_cast<uint4*>(h);
}

// ---------------- prep kernel B: modulate + demod + fp16 pack ----------------
__global__ void k_wprep(const float* __restrict__ weight) {
    const int o = blockIdx.x, b = blockIdx.y;
    const int i = threadIdx.x;  // input channel
    const float cs = 1.0f / 48.0f;  // 1/sqrt(256*9)
    const float s = g_s[b * CIN + i] * cs;
    float wv[9];
    const float* wr = weight + ((size_t)o * CIN + i) * 9;
    float ss = 0.f;
    #pragma unroll
    for (int j = 0; j < 9; j++) { wv[j] = wr[j] * s; ss += wv[j] * wv[j]; }
    // warp-shuffle reduction, one barrier
    #pragma unroll
    for (int off = 16; off; off >>= 1) ss += __shfl_xor_sync(0xffffffffu, ss, off);
    __shared__ float wsum[8];
    if ((i & 31) == 0) wsum[i >> 5] = ss;
    __syncthreads();
    float tot = wsum[0] + wsum[1] + wsum[2] + wsum[3]
              + wsum[4] + wsum[5] + wsum[6] + wsum[7];
    const float dm = rsqrtf(tot + 1e-8f);
    __half* dst = g_A + ((size_t)(b * COUT + o)) * KTOT + i;
    #pragma unroll
    for (int j = 0; j < 9; j++) dst[j * CIN] = __float2half(wv[j] * dm);
}

// ---------------- main implicit-GEMM conv (mma.sync m16n8k16, f32 acc) ----------------
// == R10 proven config, UNCHANGED ==
// CTA tile: M=128 (out ch) x N=64 (1 image row) x Kchunk=64.
// Grid (64 rows, 2 m-tiles, 8 batch) = 1024 CTAs; 8 warps (4M x 2N), warp
// tile 32x32, 2 CTAs/SM, fragment double buffering, strength-reduced
// addressing, 4-stage cp.async pipeline, issue-before-wait, wait_group 2.
constexpr uint32_t STAGE = 24576;  // 16KB A + 8KB B per stage
constexpr int NSTAGE = 4;
constexpr uint32_t SMEM_TOTAL = NSTAGE * STAGE;   // 98304
constexpr int NCHUNK = 36;

__global__ void __launch_bounds__(256, 2) k_conv(float* __restrict__ out) {
    extern __shared__ char smem[];
    const uint32_t sb = s2u(smem);
    const int tid = threadIdx.x, wid = tid >> 5, lane = tid & 31;
    const int b  = blockIdx.z;
    const int o0 = blockIdx.y * 128;
    const int y0 = blockIdx.x;          // one image row per CTA

    const __half* Ab = g_A  + ((size_t)b * COUT + o0) * KTOT;
    const __half* Xb = g_xt + (size_t)b * HW * CIN;

    const int wm = (wid >> 1) * 32;     // warp M offset (0,32,64,96)
    const int wn = (wid & 1) * 32;      // warp N offset (0,32)

    // ldmatrix lane address components
    const int a_row = wm + (lane & 15);
    const int a_kof = (lane >> 4) * 8;
    const int b_row = wn + (lane & 7) + ((lane >> 3) & 1) * 8;
    const int b_kof = (lane >> 4) * 8;

    // precomputed swizzled LDSM offsets (stage-relative)
    uint32_t offA[4][2], offB[4][2];
    #pragma unroll
    for (int ks = 0; ks < 4; ks++) {
        #pragma unroll
        for (int mi = 0; mi < 2; mi++)
            offA[ks][mi] = swz((uint32_t)((a_row + mi * 16) * 128 + (ks * 16 + a_kof) * 2));
        #pragma unroll
        for (int nh = 0; nh < 2; nh++)
            offB[ks][nh] = 16384u + swz((uint32_t)((b_row + nh * 16) * 128 + (ks * 16 + b_kof) * 2));
    }

    // per-thread load coordinates + precomputed cp.async dst offsets
    const int ld_row = tid >> 3, ld_q = tid & 7;
    uint32_t dstA[4];
    #pragma unroll
    for (int i = 0; i < 4; i++)
        dstA[i] = swz((uint32_t)((ld_row + i * 32) * 128 + ld_q * 16));

    // A source base pointers: advance by ci*64 halves per chunk
    const __half* pAbase[4];
    #pragma unroll
    for (int i = 0; i < 4; i++)
        pAbase[i] = Ab + (size_t)(ld_row + i * 32) * KTOT + ld_q * 8;

    // B issue-side state (recomputed at tap boundaries)
    const __half* pB[2];
    bool okB[2];

    float acc[2][4][4];
    #pragma unroll
    for (int mi = 0; mi < 2; mi++)
        #pragma unroll
        for (int ni = 0; ni < 4; ni++)
            #pragma unroll
            for (int j = 0; j < 4; j++) acc[mi][ni][j] = 0.f;

    auto issue = [&](int j) {
        const uint32_t base = sb + (uint32_t)(j & 3) * STAGE;
        if ((j & 3) == 0) {  // tap boundary: recompute B pointers + predicates
            const int t = j >> 2;
            const int dy = t / 3 - 1, dx = t % 3 - 1;
            const int ys = y0 + dy;
            #pragma unroll
            for (int i = 0; i < 2; i++) {
                const int xs = ld_row + i * 32 + dx;
                okB[i] = ((unsigned)ys < 64u) & ((unsigned)xs < 64u);
                pB[i] = Xb + ((size_t)ys * 64 + xs) * CIN + ld_q * 8;
            }
        }
        const int koff = j * 64;        // A k-offset: tap*CIN + cc*64 == j*64
        #pragma unroll
        for (int i = 0; i < 4; i++)
            cp16(base + dstA[i], pAbase[i] + koff, 16);
        const int coff = (j & 3) * 64;  // B channel offset within tap
        #pragma unroll
        for (int i = 0; i < 2; i++)
            cp16(base + dstA[i] + 16384u, okB[i] ? pB[i] + coff : (const __half*)Xb,
                 okB[i] ? 16u : 0u);
        cp_commit();
    };

    issue(0);
    issue(1);

    for (int ci = 0; ci < NCHUNK; ci++) {
        // keep exactly 3 groups pending so wait_group 2 => chunk ci complete
        if (ci + 2 < NCHUNK) issue(ci + 2); else cp_commit();
        asm volatile("cp.async.wait_group 2;" ::: "memory");
        __syncthreads();

        const uint32_t S = sb + (uint32_t)(ci & 3) * STAGE;

        // fragment double buffer
        uint32_t af[2][2][4], bf[2][2][4];
        ldsm4(af[0][0], S + offA[0][0]);
        ldsm4(af[0][1], S + offA[0][1]);
        ldsm4(bf[0][0], S + offB[0][0]);
        ldsm4(bf[0][1], S + offB[0][1]);

        #pragma unroll
        for (int ks = 0; ks < 4; ks++) {
            const int cur = ks & 1, nxt = cur ^ 1;
            if (ks < 3) {
                ldsm4(af[nxt][0], S + offA[ks + 1][0]);
                ldsm4(af[nxt][1], S + offA[ks + 1][1]);
                ldsm4(bf[nxt][0], S + offB[ks + 1][0]);
                ldsm4(bf[nxt][1], S + offB[ks + 1][1]);
            }
            #pragma unroll
            for (int mi = 0; mi < 2; mi++)
                #pragma unroll
                for (int ni = 0; ni < 4; ni++)
                    mma16816(acc[mi][ni], af[cur][mi],
                             bf[cur][ni >> 1][ni & 1], bf[cur][ni >> 1][(ni & 1) + 2]);
        }
        // no trailing sync: next iteration's sync separates stage reuse
    }

    // ---- epilogue: direct stores (c-frag rows lane/4, lane/4+8; cols (lane&3)*2) ----
    const int px0 = y0 * WW + wn;
    #pragma unroll
    for (int mi = 0; mi < 2; mi++) {
        const int o = o0 + wm + mi * 16 + (lane >> 2);
        float* r0 = out + ((size_t)b * COUT + o) * HW + px0;
        float* r1 = r0 + 8 * HW;
        #pragma unroll
        for (int ni = 0; ni < 4; ni++) {
            const int col = ni * 8 + (lane & 3) * 2;
            *reinterpret_cast<float2*>(r0 + col) = make_float2(acc[mi][ni][0], acc[mi][ni][1]);
            *reinterpret_cast<float2*>(r1 + col) = make_float2(acc[mi][ni][2], acc[mi][ni][3]);
        }
    }
}

// ---------------- launcher ----------------
extern "C" void kernel_launch(void* const* d_in, const int* in_sizes, int n_in,
                              void* d_out, int out_size) {
    const float* x      = (const float*)d_in[0];
    const float* style  = (const float*)d_in[1];
    const float* weight = (const float*)d_in[2];
    const float* mod_w  = (const float*)d_in[3];
    const float* mod_b  = (const float*)d_in[4];
    float* out = (float*)d_out;

    k_xt<<<dim3(128, 4, 8), 256>>>(x, style, mod_w, mod_b);   // transpose + style
    k_wprep<<<dim3(256, 8), 256>>>(weight);

    cudaFuncSetAttribute(k_conv, cudaFuncAttributeMaxDynamicSharedMemorySize, SMEM_TOTAL);
    k_conv<<<dim3(64, 2, 8), 256, SMEM_TOTAL>>>(out);
}

// round 15
// speedup vs baseline: 1.4804x; 1.4804x over previous
#include <cuda_runtime.h>
#include <cuda_fp16.h>
#include <cstdint>

#define DEVINL __device__ __forceinline__

// ---------------- problem constants ----------------
constexpr int BATCH = 8, CIN = 256, COUT = 256, HH = 64, WW = 64;
constexpr int HW   = HH * WW;      // 4096
constexpr int KTOT = 9 * CIN;      // 2304
constexpr int SDIM = 512;

// ---------------- scratch ----------------
__device__ __align__(256) __half g_A [BATCH * COUT * KTOT];   // modulated weights, [b][o][tap*256+c]
__device__ __align__(256) __half g_xt[BATCH * HW * CIN];      // x transposed: [b][pixel][channel]
__device__ float g_s[BATCH * CIN];

// ---------------- helpers ----------------
DEVINL uint32_t s2u(const void* p) {
    uint32_t a;
    asm("{ .reg .u64 t; cvta.to.shared.u64 t, %1; cvt.u32.u64 %0, t; }" : "=r"(a) : "l"(p));
    return a;
}
DEVINL uint32_t swz(uint32_t o) { return o ^ ((o >> 3) & 0x70); }  // 128B XOR swizzle

DEVINL void cp16(uint32_t dst, const void* src, uint32_t sz) {
    asm volatile("cp.async.cg.shared.global [%0], [%1], 16, %2;"
                 :: "r"(dst), "l"(src), "r"(sz));
}
DEVINL void cp_commit() { asm volatile("cp.async.commit_group;"); }

DEVINL void ldsm4(uint32_t* r, uint32_t addr) {
    asm volatile("ldmatrix.sync.aligned.m8n8.x4.shared.b16 {%0,%1,%2,%3}, [%4];"
                 : "=r"(r[0]), "=r"(r[1]), "=r"(r[2]), "=r"(r[3]) : "r"(addr));
}
DEVINL void mma16816(float* c, const uint32_t* a, uint32_t b0, uint32_t b1) {
    asm volatile("mma.sync.aligned.m16n8k16.row.col.f32.f16.f16.f32 "
                 "{%0,%1,%2,%3}, {%4,%5,%6,%7}, {%8,%9}, {%0,%1,%2,%3};"
                 : "+f"(c[0]), "+f"(c[1]), "+f"(c[2]), "+f"(c[3])
                 : "r"(a[0]), "r"(a[1]), "r"(a[2]), "r"(a[3]), "r"(b0), "r"(b1));
}

// ---------------- prep kernel 1: style modulation s[b][c] ----------------
// One warp per output channel; 32 lanes parallel over the 512-dim reduction.
__global__ void k_style(const float* __restrict__ style, const float* __restrict__ mod_w,
                        const float* __restrict__ mod_b) {
    __shared__ float st[SDIM];
    const int b = blockIdx.y;
    for (int d = threadIdx.x; d < SDIM; d += blockDim.x) st[d] = style[b * SDIM + d];
    __syncthreads();
    const int w = threadIdx.x >> 5, lid = threadIdx.x & 31;
    const int c = blockIdx.x * 8 + w;
    const float* wr = mod_w + (size_t)c * SDIM;
    float acc = 0.f;
    for (int d = lid; d < SDIM; d += 32) acc += st[d] * wr[d];
    #pragma unroll
    for (int o = 16; o; o >>= 1) acc += __shfl_xor_sync(0xffffffffu, acc, o);
    if (lid == 0) g_s[b * CIN + c] = acc * 0.04419417382415922f /*1/sqrt(512)*/ + mod_b[c];
}

// ---------------- prep kernel 2: x transpose, 16B-coalesced stores ----------
// Block: 32 px x 64 ch, 256 threads.
__global__ void k_xt(const float* __restrict__ x) {
    __shared__ float tile[64][33];
    const int b  = blockIdx.z;
    const int c0 = blockIdx.y * 64;
    const int p0 = blockIdx.x * 32;
    const int t  = threadIdx.x;

    // load: warp ty handles 8 channels, lanes = px (128B coalesced per warp)
    const int tx = t & 31, ty = t >> 5;
    #pragma unroll
    for (int j = 0; j < 8; j++)
        tile[ty * 8 + j][tx] = x[((size_t)b * CIN + c0 + ty * 8 + j) * HW + p0 + tx];
    __syncthreads();

    // store: thread = (px = t>>3, q = t&7) -> 8 halves = 16B coalesced
    const int px = t >> 3, q = t & 7;
    __half h[8];
    #pragma unroll
    for (int j = 0; j < 8; j++)
        h[j] = __float2half(tile[q * 8 + j][px]);
    *reinterpret_cast<uint4*>(
        &g_xt[((size_t)b * HW + p0 + px) * CIN + c0 + q * 8]) = *reinterpret_cast<uint4*>(h);
}

// ---------------- prep kernel 3: modulate + demod + fp16 pack ----------------
__global__ void k_wprep(const float* __restrict__ weight) {
    const int o = blockIdx.x, b = blockIdx.y;
    const int i = threadIdx.x;  // input channel
    const float cs = 1.0f / 48.0f;  // 1/sqrt(256*9)
    const float s = g_s[b * CIN + i] * cs;
    float wv[9];
    const float* wr = weight + ((size_t)o * CIN + i) * 9;
    float ss = 0.f;
    #pragma unroll
    for (int j = 0; j < 9; j++) { wv[j] = wr[j] * s; ss += wv[j] * wv[j]; }
    // warp-shuffle reduction, one barrier
    #pragma unroll
    for (int off = 16; off; off >>= 1) ss += __shfl_xor_sync(0xffffffffu, ss, off);
    __shared__ float wsum[8];
    if ((i & 31) == 0) wsum[i >> 5] = ss;
    __syncthreads();
    float tot = wsum[0] + wsum[1] + wsum[2] + wsum[3]
              + wsum[4] + wsum[5] + wsum[6] + wsum[7];
    const float dm = rsqrtf(tot + 1e-8f);
    __half* dst = g_A + ((size_t)(b * COUT + o)) * KTOT + i;
    #pragma unroll
    for (int j = 0; j < 9; j++) dst[j * CIN] = __float2half(wv[j] * dm);
}

// ---------------- main implicit-GEMM conv (mma.sync m16n8k16, f32 acc) ----------------
// == R10 proven config, UNCHANGED ==
// CTA tile: M=128 (out ch) x N=64 (1 image row) x Kchunk=64.
// Grid (64 rows, 2 m-tiles, 8 batch) = 1024 CTAs; 8 warps (4M x 2N), warp
// tile 32x32, 2 CTAs/SM, fragment double buffering, strength-reduced
// addressing, 4-stage cp.async pipeline, issue-before-wait, wait_group 2.
constexpr uint32_t STAGE = 24576;  // 16KB A + 8KB B per stage
constexpr int NSTAGE = 4;
constexpr uint32_t SMEM_TOTAL = NSTAGE * STAGE;   // 98304
constexpr int NCHUNK = 36;

__global__ void __launch_bounds__(256, 2) k_conv(float* __restrict__ out) {
    extern __shared__ char smem[];
    const uint32_t sb = s2u(smem);
    const int tid = threadIdx.x, wid = tid >> 5, lane = tid & 31;
    const int b  = blockIdx.z;
    const int o0 = blockIdx.y * 128;
    const int y0 = blockIdx.x;          // one image row per CTA

    const __half* Ab = g_A  + ((size_t)b * COUT + o0) * KTOT;
    const __half* Xb = g_xt + (size_t)b * HW * CIN;

    const int wm = (wid >> 1) * 32;     // warp M offset (0,32,64,96)
    const int wn = (wid & 1) * 32;      // warp N offset (0,32)

    // ldmatrix lane address components
    const int a_row = wm + (lane & 15);
    const int a_kof = (lane >> 4) * 8;
    const int b_row = wn + (lane & 7) + ((lane >> 3) & 1) * 8;
    const int b_kof = (lane >> 4) * 8;

    // precomputed swizzled LDSM offsets (stage-relative)
    uint32_t offA[4][2], offB[4][2];
    #pragma unroll
    for (int ks = 0; ks < 4; ks++) {
        #pragma unroll
        for (int mi = 0; mi < 2; mi++)
            offA[ks][mi] = swz((uint32_t)((a_row + mi * 16) * 128 + (ks * 16 + a_kof) * 2));
        #pragma unroll
        for (int nh = 0; nh < 2; nh++)
            offB[ks][nh] = 16384u + swz((uint32_t)((b_row + nh * 16) * 128 + (ks * 16 + b_kof) * 2));
    }

    // per-thread load coordinates + precomputed cp.async dst offsets
    const int ld_row = tid >> 3, ld_q = tid & 7;
    uint32_t dstA[4];
    #pragma unroll
    for (int i = 0; i < 4; i++)
        dstA[i] = swz((uint32_t)((ld_row + i * 32) * 128 + ld_q * 16));

    // A source base pointers: advance by ci*64 halves per chunk
    const __half* pAbase[4];
    #pragma unroll
    for (int i = 0; i < 4; i++)
        pAbase[i] = Ab + (size_t)(ld_row + i * 32) * KTOT + ld_q * 8;

    // B issue-side state (recomputed at tap boundaries)
    const __half* pB[2];
    bool okB[2];

    float acc[2][4][4];
    #pragma unroll
    for (int mi = 0; mi < 2; mi++)
        #pragma unroll
        for (int ni = 0; ni < 4; ni++)
            #pragma unroll
            for (int j = 0; j < 4; j++) acc[mi][ni][j] = 0.f;

    auto issue = [&](int j) {
        const uint32_t base = sb + (uint32_t)(j & 3) * STAGE;
        if ((j & 3) == 0) {  // tap boundary: recompute B pointers + predicates
            const int t = j >> 2;
            const int dy = t / 3 - 1, dx = t % 3 - 1;
            const int ys = y0 + dy;
            #pragma unroll
            for (int i = 0; i < 2; i++) {
                const int xs = ld_row + i * 32 + dx;
                okB[i] = ((unsigned)ys < 64u) & ((unsigned)xs < 64u);
                pB[i] = Xb + ((size_t)ys * 64 + xs) * CIN + ld_q * 8;
            }
        }
        const int koff = j * 64;        // A k-offset: tap*CIN + cc*64 == j*64
        #pragma unroll
        for (int i = 0; i < 4; i++)
            cp16(base + dstA[i], pAbase[i] + koff, 16);
        const int coff = (j & 3) * 64;  // B channel offset within tap
        #pragma unroll
        for (int i = 0; i < 2; i++)
            cp16(base + dstA[i] + 16384u, okB[i] ? pB[i] + coff : (const __half*)Xb,
                 okB[i] ? 16u : 0u);
        cp_commit();
    };

    issue(0);
    issue(1);

    for (int ci = 0; ci < NCHUNK; ci++) {
        // keep exactly 3 groups pending so wait_group 2 => chunk ci complete
        if (ci + 2 < NCHUNK) issue(ci + 2); else cp_commit();
        asm volatile("cp.async.wait_group 2;" ::: "memory");
        __syncthreads();

        const uint32_t S = sb + (uint32_t)(ci & 3) * STAGE;

        // fragment double buffer
        uint32_t af[2][2][4], bf[2][2][4];
        ldsm4(af[0][0], S + offA[0][0]);
        ldsm4(af[0][1], S + offA[0][1]);
        ldsm4(bf[0][0], S + offB[0][0]);
        ldsm4(bf[0][1], S + offB[0][1]);

        #pragma unroll
        for (int ks = 0; ks < 4; ks++) {
            const int cur = ks & 1, nxt = cur ^ 1;
            if (ks < 3) {
                ldsm4(af[nxt][0], S + offA[ks + 1][0]);
                ldsm4(af[nxt][1], S + offA[ks + 1][1]);
                ldsm4(bf[nxt][0], S + offB[ks + 1][0]);
                ldsm4(bf[nxt][1], S + offB[ks + 1][1]);
            }
            #pragma unroll
            for (int mi = 0; mi < 2; mi++)
                #pragma unroll
                for (int ni = 0; ni < 4; ni++)
                    mma16816(acc[mi][ni], af[cur][mi],
                             bf[cur][ni >> 1][ni & 1], bf[cur][ni >> 1][(ni & 1) + 2]);
        }
        // no trailing sync: next iteration's sync separates stage reuse
    }

    // ---- epilogue: direct stores (c-frag rows lane/4, lane/4+8; cols (lane&3)*2) ----
    const int px0 = y0 * WW + wn;
    #pragma unroll
    for (int mi = 0; mi < 2; mi++) {
        const int o = o0 + wm + mi * 16 + (lane >> 2);
        float* r0 = out + ((size_t)b * COUT + o) * HW + px0;
        float* r1 = r0 + 8 * HW;
        #pragma unroll
        for (int ni = 0; ni < 4; ni++) {
            const int col = ni * 8 + (lane & 3) * 2;
            *reinterpret_cast<float2*>(r0 + col) = make_float2(acc[mi][ni][0], acc[mi][ni][1]);
            *reinterpret_cast<float2*>(r1 + col) = make_float2(acc[mi][ni][2], acc[mi][ni][3]);
        }
    }
}

// ---------------- launcher ----------------
extern "C" void kernel_launch(void* const* d_in, const int* in_sizes, int n_in,
                              void* d_out, int out_size) {
    const float* x      = (const float*)d_in[0];
    const float* style  = (const float*)d_in[1];
    const float* weight = (const float*)d_in[2];
    const float* mod_w  = (const float*)d_in[3];
    const float* mod_b  = (const float*)d_in[4];
    float* out = (float*)d_out;

    k_style<<<dim3(32, 8), 256>>>(style, mod_w, mod_b);
    k_xt<<<dim3(128, 4, 8), 256>>>(x);
    k_wprep<<<dim3(256, 8), 256>>>(weight);

    cudaFuncSetAttribute(k_conv, cudaFuncAttributeMaxDynamicSharedMemorySize, SMEM_TOTAL);
    k_conv<<<dim3(64, 2, 8), 256, SMEM_TOTAL>>>(out);
}